// round 3
// baseline (speedup 1.0000x reference)
#include <cuda_runtime.h>
#include <math.h>

#define Nn 4096
#define Dd 256
#define Ss 32
#define Kk 4
#define MAXNBR 256
#define ETA 0.5f

// ---- static device scratch (no allocations allowed) ----
__device__ int   g_cnt[Nn];
__device__ int   g_nbr[Nn][MAXNBR];      // 4 MB
__device__ float g_Z[Kk][Nn][Ss];        // 2 MB
__device__ float g_G[Kk][Nn][Ss];        // 2 MB

// ---------------------------------------------------------------------------
// Kernel 1: build per-row neighbor lists from the dense adjacency mask.
// 1 warp per row; ballot + popc gives a sorted, deterministic compaction.
// ---------------------------------------------------------------------------
__global__ void build_adj(const float* __restrict__ mask) {
    int warp = threadIdx.x >> 5;
    int lane = threadIdx.x & 31;
    int row  = blockIdx.x * 4 + warp;
    const float* mrow = mask + (size_t)row * Nn;
    int base = 0;
    for (int c0 = 0; c0 < Nn; c0 += 32) {
        float v = mrow[c0 + lane];
        bool p = (v > 0.5f);
        unsigned b = __ballot_sync(0xffffffffu, p);
        if (p) {
            int pos = base + __popc(b & ((1u << lane) - 1u));
            if (pos < MAXNBR) g_nbr[row][pos] = c0 + lane;
        }
        base += __popc(b);
    }
    if (lane == 0) g_cnt[row] = (base < MAXNBR) ? base : MAXNBR;
}

// ---------------------------------------------------------------------------
// Kernel 2: Z[k][i][s] = sum_d H[i][d] * U[k][d][s]
// 1 block per row; 128 threads = (k,s) pairs; H row staged in shared.
// ---------------------------------------------------------------------------
__global__ void compute_Z(const float* __restrict__ H, const float* __restrict__ U) {
    __shared__ float h[Dd];
    int i = blockIdx.x;
    int t = threadIdx.x;                       // 0..127
    ((float2*)h)[t] = ((const float2*)(H + (size_t)i * Dd))[t];
    __syncthreads();
    int k = t >> 5, s = t & 31;
    const float* Uk = U + ((size_t)k * Dd) * Ss + s;
    float acc = 0.f;
#pragma unroll 8
    for (int d = 0; d < Dd; d++) acc += h[d] * Uk[(size_t)d * Ss];
    g_Z[k][i][s] = acc;
}

// ---------------------------------------------------------------------------
// Kernel 3: sparse softmax attention per (row, head).
// 1 block per row, warp k = head k. Non-neighbors contribute exactly 0
// (exp(x - 1e9) underflows to 0.0f), so iterating only neighbors is exact.
// Pass 1: scores into shared (lane = neighbor). Pass 2: lane = channel s,
// coalesced accumulation of sum_j alpha_j * Z[k][j][s].
// ---------------------------------------------------------------------------
__global__ void attn(const float* __restrict__ lp) {
    __shared__ int   snbr[MAXNBR];
    __shared__ float ssc[Kk][MAXNBR];
    __shared__ float zsh[Kk][Ss];
    __shared__ int   scnt;

    int i = blockIdx.x;
    int t = threadIdx.x;
    int k = t >> 5, lane = t & 31;

    if (t == 0) scnt = g_cnt[i];
    zsh[k][lane] = g_Z[k][i][lane] * expf(lp[k * Ss + lane]);
    __syncthreads();
    int cnt = scnt;
    for (int j = t; j < cnt; j += 128) snbr[j] = g_nbr[i][j];
    __syncthreads();

    const float inv = 0.17677669529663687f;   // 1/sqrt(32)

    // pass 1: scores + running max (lane = neighbor index mod 32)
    float lmax = -1e30f;
    for (int j = lane; j < cnt; j += 32) {
        const float* zj = g_Z[k][snbr[j]];
        float sc = 0.f;
#pragma unroll
        for (int s = 0; s < Ss; s++) sc += zsh[k][s] * zj[s];
        sc *= inv;
        ssc[k][j] = sc;
        lmax = fmaxf(lmax, sc);
    }
#pragma unroll
    for (int o = 16; o; o >>= 1) lmax = fmaxf(lmax, __shfl_xor_sync(0xffffffffu, lmax, o));

    // exponentiate + sum
    float lsum = 0.f;
    for (int j = lane; j < cnt; j += 32) {
        float e = expf(ssc[k][j] - lmax);
        ssc[k][j] = e;
        lsum += e;
    }
#pragma unroll
    for (int o = 16; o; o >>= 1) lsum += __shfl_xor_sync(0xffffffffu, lsum, o);
    __syncwarp();
    float rinv = 1.f / lsum;

    // pass 2: lane = channel s, coalesced Z loads, weights broadcast from smem
    float acc = 0.f;
    int j = 0;
    for (; j + 4 <= cnt; j += 4) {
        float w0 = ssc[k][j + 0], w1 = ssc[k][j + 1];
        float w2 = ssc[k][j + 2], w3 = ssc[k][j + 3];
        int n0 = snbr[j + 0], n1 = snbr[j + 1], n2 = snbr[j + 2], n3 = snbr[j + 3];
        acc += w0 * g_Z[k][n0][lane];
        acc += w1 * g_Z[k][n1][lane];
        acc += w2 * g_Z[k][n2][lane];
        acc += w3 * g_Z[k][n3][lane];
    }
    for (; j < cnt; j++) acc += ssc[k][j] * g_Z[k][snbr[j]][lane];

    g_G[k][i][lane] = acc * rinv;
}

// ---------------------------------------------------------------------------
// Kernel 4: H_out = softthresh(H + ETA * sum_k G[k] @ U[k]^T, threshold)
// 1 warp per row; lane owns 8 output dims; U read as float4 (L1-resident).
// ---------------------------------------------------------------------------
__global__ void finalize(const float* __restrict__ H, const float* __restrict__ U,
                         const float* __restrict__ thr, float* __restrict__ out) {
    __shared__ float sg[4][Kk * Ss];
    int w = threadIdx.x >> 5, lane = threadIdx.x & 31;
    int i = blockIdx.x * 4 + w;
#pragma unroll
    for (int k = 0; k < Kk; k++) sg[w][k * Ss + lane] = g_G[k][i][lane];
    __syncwarp();

#pragma unroll
    for (int c = 0; c < 8; c++) {
        int d = c * 32 + lane;
        float acc = 0.f;
#pragma unroll
        for (int k = 0; k < Kk; k++) {
            const float4* u4 = (const float4*)(U + ((size_t)k * Dd + d) * Ss);
            const float*  gk = &sg[w][k * Ss];
#pragma unroll
            for (int q = 0; q < 8; q++) {
                float4 uu = u4[q];
                acc += uu.x * gk[q * 4 + 0] + uu.y * gk[q * 4 + 1]
                     + uu.z * gk[q * 4 + 2] + uu.w * gk[q * 4 + 3];
            }
        }
        float hv = H[(size_t)i * Dd + d] + ETA * acc;
        float mag = fabsf(hv) - thr[d];
        mag = fmaxf(mag, 0.f);
        out[(size_t)i * Dd + d] = copysignf(mag, hv);   // sign(0)*0 == 0 either way
    }
}

// ---------------------------------------------------------------------------
// Kernel 5: orthogonality loss. One block; 16K gram entries, each a 256-dot.
// loss = sum_k ||U_k^T U_k - I||_F^2 + sum_{k<l} ||U_k^T U_l||_F^2
// ---------------------------------------------------------------------------
__global__ void orth_loss(const float* __restrict__ U, float* __restrict__ out) {
    __shared__ float red[256];
    int t = threadIdx.x;
    float local = 0.f;
    for (int idx = t; idx < Kk * Kk * Ss * Ss; idx += 256) {
        int b = idx & 31;
        int a = (idx >> 5) & 31;
        int l = (idx >> 10) & 3;
        int k = idx >> 12;
        if (k > l) continue;
        const float* ua = U + (size_t)k * Dd * Ss + a;
        const float* ub = U + (size_t)l * Dd * Ss + b;
        float c = 0.f;
#pragma unroll 8
        for (int d = 0; d < Dd; d++) c += ua[(size_t)d * Ss] * ub[(size_t)d * Ss];
        if (k == l) { float e = c - (a == b ? 1.f : 0.f); local += e * e; }
        else        { local += c * c; }
    }
    red[t] = local;
    __syncthreads();
    for (int o = 128; o; o >>= 1) {
        if (t < o) red[t] += red[t + o];
        __syncthreads();
    }
    if (t == 0) out[0] = red[0];
}

// ---------------------------------------------------------------------------
extern "C" void kernel_launch(void* const* d_in, const int* in_sizes, int n_in,
                              void* d_out, int out_size) {
    const float* H    = (const float*)d_in[0];   // [N, D]
    const float* mask = (const float*)d_in[1];   // [N, N]
    const float* U    = (const float*)d_in[2];   // [K, D, S]
    const float* lp   = (const float*)d_in[3];   // [K, S]
    const float* thr  = (const float*)d_in[4];   // [D]
    float* out = (float*)d_out;

    build_adj<<<Nn / 4, 128>>>(mask);
    compute_Z<<<Nn, 128>>>(H, U);
    attn<<<Nn, 128>>>(lp);
    finalize<<<Nn / 4, 128>>>(H, U, thr, out);
    if (out_size > Nn * Dd) orth_loss<<<1, 256>>>(U, out + (size_t)Nn * Dd);
}

// round 6
// speedup vs baseline: 2.9520x; 2.9520x over previous
#include <cuda_runtime.h>
#include <math.h>

#define Nn 4096
#define Dd 256
#define Ss 32
#define Kk 4
#define KS 128           // K*S combined column dim
#define MAXNBR 256
#define ETA 0.5f

// ---- static device scratch (no allocations allowed) ----
__device__ int   g_cnt[Nn];
__device__ int   g_nbr[Nn][MAXNBR];      // 4 MB
__device__ float g_Z2[Nn][KS];           // 2 MB   Z[i][k*32+s]
__device__ float g_G2[Nn][KS];           // 2 MB   aggregated per-head output
__device__ float g_Uw[Dd][KS];           // 128 KB U viewed [d][ks]   (for Z = H @ Uw)
__device__ float g_Ut[KS][Dd];           // 128 KB U viewed [ks][d]   (for out = G @ Ut)
__device__ float g_orth[16];

__device__ __constant__ int c_pk[10] = {0,0,0,0,1,1,1,2,2,3};
__device__ __constant__ int c_pl[10] = {0,1,2,3,1,2,3,2,3,3};

static __device__ __forceinline__ void fma4(float4& a, const float4& u, float g) {
    a.x += u.x * g; a.y += u.y * g; a.z += u.z * g; a.w += u.w * g;
}

// ---------------------------------------------------------------------------
// K0: build both transposed views of U. U[k][d][s] -> Uw[d][ks], Ut[ks][d].
// ---------------------------------------------------------------------------
__global__ void prep_U(const float* __restrict__ U) {
    int idx = blockIdx.x * 256 + threadIdx.x;        // grid 128 -> 32768 elems
    int k = idx >> 13;
    int r = idx & 8191;
    int d = r >> 5;
    int s = r & 31;
    float v = U[idx];
    g_Uw[d][k * Ss + s] = v;
    g_Ut[k * Ss + s][d] = v;
}

// ---------------------------------------------------------------------------
// K1: neighbor lists from dense mask. 1 warp/row, float4 loads + 4 ballots.
// ---------------------------------------------------------------------------
__global__ void build_adj(const float* __restrict__ mask) {
    int warp = threadIdx.x >> 5;
    int lane = threadIdx.x & 31;
    int row  = blockIdx.x * 8 + warp;                // grid 512, block 256
    const float4* m4 = (const float4*)(mask + (size_t)row * Nn);
    unsigned lt = (1u << lane) - 1u;
    int base = 0;
    for (int c = 0; c < Nn / 4; c += 32) {
        float4 v = m4[c + lane];
        int e0 = (c + lane) * 4;
        bool p;
        unsigned b;
        p = v.x > 0.5f; b = __ballot_sync(0xffffffffu, p);
        if (p) { int pos = base + __popc(b & lt); if (pos < MAXNBR) g_nbr[row][pos] = e0 + 0; }
        base += __popc(b);
        p = v.y > 0.5f; b = __ballot_sync(0xffffffffu, p);
        if (p) { int pos = base + __popc(b & lt); if (pos < MAXNBR) g_nbr[row][pos] = e0 + 1; }
        base += __popc(b);
        p = v.z > 0.5f; b = __ballot_sync(0xffffffffu, p);
        if (p) { int pos = base + __popc(b & lt); if (pos < MAXNBR) g_nbr[row][pos] = e0 + 2; }
        base += __popc(b);
        p = v.w > 0.5f; b = __ballot_sync(0xffffffffu, p);
        if (p) { int pos = base + __popc(b & lt); if (pos < MAXNBR) g_nbr[row][pos] = e0 + 3; }
        base += __popc(b);
    }
    if (lane == 0) g_cnt[row] = (base < MAXNBR) ? base : MAXNBR;
}

// ---------------------------------------------------------------------------
// K2: Z2[i][ks] = sum_d H[i][d] * Uw[d][ks].  Register-tiled GEMM:
// 32-row block tile, thread = (float4 of ks) x (4 rows), H staged in smem.
// ---------------------------------------------------------------------------
__global__ void compute_Z(const float* __restrict__ H) {
    __shared__ float Hs[32][Dd];                     // 32 KB
    int i0 = blockIdx.x * 32;                        // grid 128, block 256
    int t = threadIdx.x;
    const float4* Hf4 = (const float4*)H;
    float4* Hs4 = (float4*)&Hs[0][0];
#pragma unroll
    for (int q = 0; q < 8; q++)
        Hs4[q * 256 + t] = Hf4[(size_t)i0 * 64 + q * 256 + t];
    __syncthreads();

    int tx = t & 31, ty = t >> 5;                    // tx: ks4 group, ty: 8 row-groups
    int r0 = ty * 4;
    float4 a0 = {0,0,0,0}, a1 = {0,0,0,0}, a2 = {0,0,0,0}, a3 = {0,0,0,0};
#pragma unroll 4
    for (int d = 0; d < Dd; d++) {
        float4 u = *(const float4*)&g_Uw[d][tx * 4];
        fma4(a0, u, Hs[r0 + 0][d]);
        fma4(a1, u, Hs[r0 + 1][d]);
        fma4(a2, u, Hs[r0 + 2][d]);
        fma4(a3, u, Hs[r0 + 3][d]);
    }
    float4* Z4 = (float4*)&g_Z2[0][0];
    Z4[(size_t)(i0 + r0 + 0) * 32 + tx] = a0;
    Z4[(size_t)(i0 + r0 + 1) * 32 + tx] = a1;
    Z4[(size_t)(i0 + r0 + 2) * 32 + tx] = a2;
    Z4[(size_t)(i0 + r0 + 3) * 32 + tx] = a3;
}

// ---------------------------------------------------------------------------
// K3: sparse attention, single-pass online softmax, smem tile staging.
// 1 block/row, warp k = head k. Exact: non-neighbor exp underflows to 0.
// ---------------------------------------------------------------------------
__global__ void attn(const float* __restrict__ lp) {
    __shared__ int   snbr[MAXNBR];
    __shared__ float Zt[Kk][32][33];                 // 33-pad: conflict-free both axes
    __shared__ float ew[Kk][32];
    __shared__ float zq[Kk][Ss];
    __shared__ int   scnt;

    int i = blockIdx.x;
    int t = threadIdx.x;
    int k = t >> 5, lane = t & 31;

    if (t == 0) scnt = g_cnt[i];
    zq[k][lane] = g_Z2[i][t] * expf(lp[t]);          // t == k*32+lane
    __syncthreads();
    int cnt = scnt;
    for (int j = t; j < cnt; j += 128) snbr[j] = g_nbr[i][j];
    __syncthreads();

    const float inv = 0.17677669529663687f;          // 1/sqrt(32)
    float M = -3.0e38f, L = 0.f, acc = 0.f;
    int kbase = k << 5;

    for (int t0 = 0; t0 < cnt; t0 += 32) {
        int tl = min(32, cnt - t0);
        // stage tile: coalesced 128B row-slices
        if (tl == 32) {
#pragma unroll 8
            for (int j = 0; j < 32; j++)
                Zt[k][j][lane] = g_Z2[snbr[t0 + j]][kbase + lane];
        } else {
            for (int j = 0; j < tl; j++)
                Zt[k][j][lane] = g_Z2[snbr[t0 + j]][kbase + lane];
        }
        __syncwarp();

        // scores: lane = neighbor in tile
        float sc = -3.0e38f;
        if (lane < tl) {
            float s0 = 0.f;
#pragma unroll
            for (int s = 0; s < Ss; s++) s0 += zq[k][s] * Zt[k][lane][s];
            sc = s0 * inv;
        }
        float mt = sc;
#pragma unroll
        for (int o = 16; o; o >>= 1) mt = fmaxf(mt, __shfl_xor_sync(0xffffffffu, mt, o));
        float newM = fmaxf(M, mt);
        float e = (lane < tl) ? expf(sc - newM) : 0.f;
        ew[k][lane] = e;
        float es = e;
#pragma unroll
        for (int o = 16; o; o >>= 1) es += __shfl_xor_sync(0xffffffffu, es, o);
        float scale = expf(M - newM);                // first tile: exp(-huge) = 0
        L = L * scale + es;
        acc *= scale;
        M = newM;
        __syncwarp();

        // accumulate: lane = channel s (coalesced smem)
        if (tl == 32) {
#pragma unroll 8
            for (int j = 0; j < 32; j++) acc += ew[k][j] * Zt[k][j][lane];
        } else {
            for (int j = 0; j < tl; j++) acc += ew[k][j] * Zt[k][j][lane];
        }
        __syncwarp();
    }
    g_G2[i][t] = acc / L;
}

// ---------------------------------------------------------------------------
// K4: out = softthresh(H + ETA * G2 @ Ut, thr). Register-tiled GEMM:
// 32-row tile, thread = (float4 of d) x (8 rows), G staged in smem.
// ---------------------------------------------------------------------------
__global__ void finalize(const float* __restrict__ H, const float* __restrict__ thr,
                         float* __restrict__ out) {
    __shared__ float Gs[32][KS];                     // 16 KB
    int i0 = blockIdx.x * 32;                        // grid 128, block 256
    int t = threadIdx.x;
    const float4* Gf4 = (const float4*)&g_G2[0][0];
    float4* Gs4 = (float4*)&Gs[0][0];
#pragma unroll
    for (int q = 0; q < 4; q++)
        Gs4[q * 256 + t] = Gf4[(size_t)i0 * 32 + q * 256 + t];
    __syncthreads();

    int tx = t & 63, ty = t >> 6;                    // tx: d4 group, ty: 4 row-groups
    int r0 = ty * 8;
    float4 acc[8];
#pragma unroll
    for (int r = 0; r < 8; r++) acc[r] = make_float4(0, 0, 0, 0);

#pragma unroll 2
    for (int ks = 0; ks < KS; ks++) {
        float4 u = *(const float4*)&g_Ut[ks][tx * 4];
#pragma unroll
        for (int r = 0; r < 8; r++) fma4(acc[r], u, Gs[r0 + r][ks]);
    }

    const float4* Hf4 = (const float4*)H;
    const float4* Tf4 = (const float4*)thr;
    float4* Of4 = (float4*)out;
    float4 th = Tf4[tx];
#pragma unroll
    for (int r = 0; r < 8; r++) {
        int i = i0 + r0 + r;
        float4 h = Hf4[(size_t)i * 64 + tx];
        float4 v;
        v.x = h.x + ETA * acc[r].x;
        v.y = h.y + ETA * acc[r].y;
        v.z = h.z + ETA * acc[r].z;
        v.w = h.w + ETA * acc[r].w;
        float m;
        m = fmaxf(fabsf(v.x) - th.x, 0.f); v.x = copysignf(m, v.x);
        m = fmaxf(fabsf(v.y) - th.y, 0.f); v.y = copysignf(m, v.y);
        m = fmaxf(fabsf(v.z) - th.z, 0.f); v.z = copysignf(m, v.z);
        m = fmaxf(fabsf(v.w) - th.w, 0.f); v.w = copysignf(m, v.w);
        Of4[(size_t)i * 64 + tx] = v;
    }
}

// ---------------------------------------------------------------------------
// K5: orthogonality loss, one block per (k<=l) pair, smem-staged Ut slabs,
// 2x2 register tiles. Deterministic fixed-order reductions.
// ---------------------------------------------------------------------------
__global__ void orth_pair() {
    __shared__ float As[32][129];
    __shared__ float Bs[32][129];
    __shared__ float red[256];
    int p = blockIdx.x;                              // grid 10, block 256
    int k = c_pk[p], l = c_pl[p];
    int t = threadIdx.x;
    int ga = t >> 4, gb = t & 15;
    int a0 = ga * 2, b0 = gb * 2;
    float c00 = 0, c01 = 0, c10 = 0, c11 = 0;

    for (int d0 = 0; d0 < Dd; d0 += 128) {
        __syncthreads();
        for (int idx = t; idx < 32 * 128; idx += 256) {
            int a = idx >> 7, d = idx & 127;
            As[a][d] = g_Ut[k * 32 + a][d0 + d];
            Bs[a][d] = g_Ut[l * 32 + a][d0 + d];
        }
        __syncthreads();
#pragma unroll 4
        for (int d = 0; d < 128; d++) {
            float av0 = As[a0][d], av1 = As[a0 + 1][d];
            float bv0 = Bs[b0][d], bv1 = Bs[b0 + 1][d];
            c00 += av0 * bv0; c01 += av0 * bv1;
            c10 += av1 * bv0; c11 += av1 * bv1;
        }
    }

    float local;
    if (k == l) {
        float e;
        local = 0.f;
        e = c00 - ((a0     == b0    ) ? 1.f : 0.f); local += e * e;
        e = c01 - ((a0     == b0 + 1) ? 1.f : 0.f); local += e * e;
        e = c10 - ((a0 + 1 == b0    ) ? 1.f : 0.f); local += e * e;
        e = c11 - ((a0 + 1 == b0 + 1) ? 1.f : 0.f); local += e * e;
    } else {
        local = c00 * c00 + c01 * c01 + c10 * c10 + c11 * c11;
    }
    red[t] = local;
    __syncthreads();
    for (int o = 128; o; o >>= 1) {
        if (t < o) red[t] += red[t + o];
        __syncthreads();
    }
    if (t == 0) g_orth[p] = red[0];
}

__global__ void orth_reduce(float* __restrict__ out) {
    if (threadIdx.x == 0) {
        float s = 0.f;
        for (int p = 0; p < 10; p++) s += g_orth[p];
        out[0] = s;
    }
}

// ---------------------------------------------------------------------------
extern "C" void kernel_launch(void* const* d_in, const int* in_sizes, int n_in,
                              void* d_out, int out_size) {
    const float* H    = (const float*)d_in[0];   // [N, D]
    const float* mask = (const float*)d_in[1];   // [N, N]
    const float* U    = (const float*)d_in[2];   // [K, D, S]
    const float* lp   = (const float*)d_in[3];   // [K, S]
    const float* thr  = (const float*)d_in[4];   // [D]
    float* out = (float*)d_out;

    prep_U<<<128, 256>>>(U);
    build_adj<<<512, 256>>>(mask);
    compute_Z<<<128, 256>>>(H);
    attn<<<4096, 128>>>(lp);
    finalize<<<128, 256>>>(H, thr, out);
    if (out_size > Nn * Dd) {
        orth_pair<<<10, 256>>>();
        orth_reduce<<<1, 32>>>(out + (size_t)Nn * Dd);
    }
}

// round 8
// speedup vs baseline: 4.5639x; 1.5460x over previous
#include <cuda_runtime.h>
#include <math.h>

#define Nn 4096
#define Dd 256
#define Ss 32
#define Kk 4
#define KS 128           // K*S combined column dim
#define MAXNBR 256
#define ETA 0.5f

// ---- static device scratch (no allocations allowed) ----
__device__ int   g_cnt[Nn];
__device__ int   g_nbr[Nn][MAXNBR];      // 4 MB
__device__ float g_Z2[Nn][KS];           // 2 MB   Z[i][k*32+s]
__device__ float g_G2[Nn][KS];           // 2 MB
__device__ float g_Ut[KS][Dd];           // 128 KB U viewed [ks][d] (finalize/orth)
__device__ float g_orth[16];

__device__ __constant__ int c_pk[10] = {0,0,0,0,1,1,1,2,2,3};
__device__ __constant__ int c_pl[10] = {0,1,2,3,1,2,3,2,3,3};

static __device__ __forceinline__ void fma4(float4& a, const float4& u, float g) {
    a.x += u.x * g; a.y += u.y * g; a.z += u.z * g; a.w += u.w * g;
}

// ===========================================================================
// Launch 1 (fused): blocks [0,512) build_adj | [512,640) compute_Z | [640,768) Ut
// Mutually independent: compute_Z reads the ORIGINAL U layout (float4 along s
// is contiguous), so no transpose dependency.
// ===========================================================================
__global__ void fused_prep(const float* __restrict__ mask,
                           const float* __restrict__ H,
                           const float* __restrict__ U) {
    __shared__ float Hs[32][Dd];                     // used by compute_Z branch
    int b = blockIdx.x;
    int t = threadIdx.x;

    if (b < 512) {
        // ---- build_adj: 1 warp per row, float4 + 4 ballots ----
        int warp = t >> 5, lane = t & 31;
        int row  = b * 8 + warp;
        const float4* m4 = (const float4*)(mask + (size_t)row * Nn);
        unsigned lt = (1u << lane) - 1u;
        int base = 0;
#pragma unroll 2
        for (int c = 0; c < Nn / 4; c += 32) {
            float4 v = __ldcs(&m4[c + lane]);
            int e0 = (c + lane) * 4;
            bool p; unsigned bb;
            p = v.x > 0.5f; bb = __ballot_sync(0xffffffffu, p);
            if (p) { int pos = base + __popc(bb & lt); if (pos < MAXNBR) g_nbr[row][pos] = e0 + 0; }
            base += __popc(bb);
            p = v.y > 0.5f; bb = __ballot_sync(0xffffffffu, p);
            if (p) { int pos = base + __popc(bb & lt); if (pos < MAXNBR) g_nbr[row][pos] = e0 + 1; }
            base += __popc(bb);
            p = v.z > 0.5f; bb = __ballot_sync(0xffffffffu, p);
            if (p) { int pos = base + __popc(bb & lt); if (pos < MAXNBR) g_nbr[row][pos] = e0 + 2; }
            base += __popc(bb);
            p = v.w > 0.5f; bb = __ballot_sync(0xffffffffu, p);
            if (p) { int pos = base + __popc(bb & lt); if (pos < MAXNBR) g_nbr[row][pos] = e0 + 3; }
            base += __popc(bb);
        }
        if (lane == 0) g_cnt[row] = (base < MAXNBR) ? base : MAXNBR;
    } else if (b < 640) {
        // ---- compute_Z: Z2[i][ks] = sum_d H[i][d] * U[k][d][s] ----
        int i0 = (b - 512) * 32;
        const float4* Hf4 = (const float4*)H;
        float4* Hs4 = (float4*)&Hs[0][0];
#pragma unroll
        for (int q = 0; q < 8; q++)
            Hs4[q * 256 + t] = Hf4[(size_t)i0 * 64 + q * 256 + t];
        __syncthreads();

        int tx = t & 31, ty = t >> 5;                // tx: ks4 group, ty: 8 row-groups
        int k = tx >> 3, s4 = tx & 7;
        const float4* Up = (const float4*)(U + ((size_t)k * Dd) * Ss + s4 * 4);
        int r0 = ty * 4;
        float4 a0 = {0,0,0,0}, a1 = {0,0,0,0}, a2 = {0,0,0,0}, a3 = {0,0,0,0};
#pragma unroll 4
        for (int d = 0; d < Dd; d++) {
            float4 u = Up[d * 8];                    // stride Ss floats = 8 float4
            fma4(a0, u, Hs[r0 + 0][d]);
            fma4(a1, u, Hs[r0 + 1][d]);
            fma4(a2, u, Hs[r0 + 2][d]);
            fma4(a3, u, Hs[r0 + 3][d]);
        }
        float4* Z4 = (float4*)&g_Z2[0][0];
        Z4[(size_t)(i0 + r0 + 0) * 32 + tx] = a0;
        Z4[(size_t)(i0 + r0 + 1) * 32 + tx] = a1;
        Z4[(size_t)(i0 + r0 + 2) * 32 + tx] = a2;
        Z4[(size_t)(i0 + r0 + 3) * 32 + tx] = a3;
    } else {
        // ---- transpose U -> Ut[ks][d] ----
        int idx = (b - 640) * 256 + t;               // 32768 elems
        int k = idx >> 13;
        int r = idx & 8191;
        int d = r >> 5;
        int s = r & 31;
        g_Ut[k * Ss + s][d] = U[idx];
    }
}

// ===========================================================================
// Launch 2: sparse attention with online softmax, double-buffered tiles.
// 1 block/row, warp k = head k. Per lane: 8 x LDG.128 cover the FULL 32x32
// tile (row = (lane>>3) + 4*it, chunk = (lane&7)*4). Tile t+1 prefetched into
// registers while tile t computes. Exact: non-neighbor exp underflows to 0.
// ===========================================================================
__global__ void attn(const float* __restrict__ lp) {
    __shared__ int   snbr[MAXNBR];
    __shared__ float Zt[Kk][32][33];                 // 33-pad: conflict-free both axes
    __shared__ float ew[Kk][32];
    __shared__ float zq[Kk][Ss];
    __shared__ int   scnt;

    int i = blockIdx.x;
    int t = threadIdx.x;
    int k = t >> 5, lane = t & 31;

    if (t == 0) scnt = g_cnt[i];
    zq[k][lane] = g_Z2[i][t] * expf(lp[t]);          // t == k*32+lane
    // zero-init this warp's tile (stale smem must be finite for 0-weight FMAs)
    for (int j = lane; j < 32 * 33; j += 32) (&Zt[k][0][0])[j] = 0.f;
    __syncthreads();
    int cnt = scnt;
    for (int j = t; j < cnt; j += 128) snbr[j] = g_nbr[i][j];
    __syncthreads();

    const float inv = 0.17677669529663687f;          // 1/sqrt(32)
    int kbase = k << 5;
    int jj = lane >> 3;                              // row-group base 0..3
    int cc = (lane & 7) * 4;                         // float4 chunk 0..28
    float M = -3.0e38f, L = 0.f;
    float a0 = 0.f, a1 = 0.f, a2 = 0.f, a3 = 0.f;

    // prefetch tile 0 into registers (8 x LDG.128 per lane = full 32x32 tile)
    float4 pv[8];
#pragma unroll
    for (int it = 0; it < 8; it++) {
        int r = jj + 4 * it;
        if (r < cnt) pv[it] = *(const float4*)&g_Z2[snbr[r]][kbase + cc];
    }

    for (int t0 = 0; t0 < cnt; t0 += 32) {
        int tl = min(32, cnt - t0);

        // commit prefetched tile to smem
#pragma unroll
        for (int it = 0; it < 8; it++) {
            int r = jj + 4 * it;
            if (r < tl) {
                Zt[k][r][cc + 0] = pv[it].x; Zt[k][r][cc + 1] = pv[it].y;
                Zt[k][r][cc + 2] = pv[it].z; Zt[k][r][cc + 3] = pv[it].w;
            }
        }
        __syncwarp();

        // prefetch NEXT tile (overlaps with compute below)
        int n0 = t0 + 32;
        if (n0 < cnt) {
#pragma unroll
            for (int it = 0; it < 8; it++) {
                int r = n0 + jj + 4 * it;
                if (r < cnt) pv[it] = *(const float4*)&g_Z2[snbr[r]][kbase + cc];
            }
        }

        // scores: lane = neighbor in tile (2 partial sums break the FFMA chain)
        float s0 = 0.f, s1 = 0.f;
#pragma unroll
        for (int s = 0; s < Ss; s += 2) {
            s0 += zq[k][s]     * Zt[k][lane][s];
            s1 += zq[k][s + 1] * Zt[k][lane][s + 1];
        }
        float sc = (lane < tl) ? (s0 + s1) * inv : -3.0e38f;

        float mt = sc;
#pragma unroll
        for (int o = 16; o; o >>= 1) mt = fmaxf(mt, __shfl_xor_sync(0xffffffffu, mt, o));
        float newM = fmaxf(M, mt);
        float e = (lane < tl) ? expf(sc - newM) : 0.f;
        ew[k][lane] = e;
        float es = e;
#pragma unroll
        for (int o = 16; o; o >>= 1) es += __shfl_xor_sync(0xffffffffu, es, o);
        float scale = expf(M - newM);                // first tile: exp(-huge) = 0
        L = L * scale + es;
        a0 *= scale; a1 *= scale; a2 *= scale; a3 *= scale;
        M = newM;
        __syncwarp();

        // accumulate: lane = channel s; full 32 (ew is 0 beyond tl, Zt finite)
#pragma unroll
        for (int j = 0; j < 32; j += 4) {
            a0 += ew[k][j + 0] * Zt[k][j + 0][lane];
            a1 += ew[k][j + 1] * Zt[k][j + 1][lane];
            a2 += ew[k][j + 2] * Zt[k][j + 2][lane];
            a3 += ew[k][j + 3] * Zt[k][j + 3][lane];
        }
        __syncwarp();                                // before next tile overwrite
    }
    g_G2[i][t] = ((a0 + a1) + (a2 + a3)) / L;
}

// ===========================================================================
// Launch 3 (fused): blocks [0,128) finalize | [128,138) orth_pair
// ===========================================================================
__global__ void fused_fin(const float* __restrict__ H, const float* __restrict__ thr,
                          float* __restrict__ out) {
    __shared__ float Gs[32][KS];                     // finalize staging (16 KB)
    __shared__ float As[32][129];
    __shared__ float Bs[32][129];
    __shared__ float red[256];
    int b = blockIdx.x;
    int t = threadIdx.x;

    if (b < 128) {
        // ---- finalize: out = softthresh(H + ETA * G2 @ Ut, thr) ----
        int i0 = b * 32;
        const float4* Gf4 = (const float4*)&g_G2[0][0];
        float4* Gs4 = (float4*)&Gs[0][0];
#pragma unroll
        for (int q = 0; q < 4; q++)
            Gs4[q * 256 + t] = Gf4[(size_t)i0 * 32 + q * 256 + t];
        __syncthreads();

        int tx = t & 63, ty = t >> 6;
        int r0 = ty * 8;
        float4 acc[8];
#pragma unroll
        for (int r = 0; r < 8; r++) acc[r] = make_float4(0, 0, 0, 0);

#pragma unroll 2
        for (int ks = 0; ks < KS; ks++) {
            float4 u = *(const float4*)&g_Ut[ks][tx * 4];
#pragma unroll
            for (int r = 0; r < 8; r++) fma4(acc[r], u, Gs[r0 + r][ks]);
        }

        const float4* Hf4 = (const float4*)H;
        const float4* Tf4 = (const float4*)thr;
        float4* Of4 = (float4*)out;
        float4 th = Tf4[tx];
#pragma unroll
        for (int r = 0; r < 8; r++) {
            int i = i0 + r0 + r;
            float4 h = Hf4[(size_t)i * 64 + tx];
            float4 v;
            v.x = h.x + ETA * acc[r].x;
            v.y = h.y + ETA * acc[r].y;
            v.z = h.z + ETA * acc[r].z;
            v.w = h.w + ETA * acc[r].w;
            float m;
            m = fmaxf(fabsf(v.x) - th.x, 0.f); v.x = copysignf(m, v.x);
            m = fmaxf(fabsf(v.y) - th.y, 0.f); v.y = copysignf(m, v.y);
            m = fmaxf(fabsf(v.z) - th.z, 0.f); v.z = copysignf(m, v.z);
            m = fmaxf(fabsf(v.w) - th.w, 0.f); v.w = copysignf(m, v.w);
            Of4[(size_t)i * 64 + tx] = v;
        }
    } else {
        // ---- orth_pair: gram block for pair p, deterministic reduction ----
        int p = b - 128;
        int k = c_pk[p], l = c_pl[p];
        int ga = t >> 4, gb = t & 15;
        int a0 = ga * 2, b0 = gb * 2;
        float c00 = 0, c01 = 0, c10 = 0, c11 = 0;

        for (int d0 = 0; d0 < Dd; d0 += 128) {
            __syncthreads();
            for (int idx = t; idx < 32 * 128; idx += 256) {
                int a = idx >> 7, d = idx & 127;
                As[a][d] = g_Ut[k * 32 + a][d0 + d];
                Bs[a][d] = g_Ut[l * 32 + a][d0 + d];
            }
            __syncthreads();
#pragma unroll 4
            for (int d = 0; d < 128; d++) {
                float av0 = As[a0][d], av1 = As[a0 + 1][d];
                float bv0 = Bs[b0][d], bv1 = Bs[b0 + 1][d];
                c00 += av0 * bv0; c01 += av0 * bv1;
                c10 += av1 * bv0; c11 += av1 * bv1;
            }
        }

        float local;
        if (k == l) {
            float e;
            local = 0.f;
            e = c00 - ((a0     == b0    ) ? 1.f : 0.f); local += e * e;
            e = c01 - ((a0     == b0 + 1) ? 1.f : 0.f); local += e * e;
            e = c10 - ((a0 + 1 == b0    ) ? 1.f : 0.f); local += e * e;
            e = c11 - ((a0 + 1 == b0 + 1) ? 1.f : 0.f); local += e * e;
        } else {
            local = c00 * c00 + c01 * c01 + c10 * c10 + c11 * c11;
        }
        red[t] = local;
        __syncthreads();
        for (int o = 128; o; o >>= 1) {
            if (t < o) red[t] += red[t + o];
            __syncthreads();
        }
        if (t == 0) g_orth[p] = red[0];
    }
}

__global__ void orth_reduce(float* __restrict__ out) {
    if (threadIdx.x == 0) {
        float s = 0.f;
        for (int p = 0; p < 10; p++) s += g_orth[p];
        out[0] = s;
    }
}

// ---------------------------------------------------------------------------
extern "C" void kernel_launch(void* const* d_in, const int* in_sizes, int n_in,
                              void* d_out, int out_size) {
    const float* H    = (const float*)d_in[0];   // [N, D]
    const float* mask = (const float*)d_in[1];   // [N, N]
    const float* U    = (const float*)d_in[2];   // [K, D, S]
    const float* lp   = (const float*)d_in[3];   // [K, S]
    const float* thr  = (const float*)d_in[4];   // [D]
    float* out = (float*)d_out;

    fused_prep<<<768, 256>>>(mask, H, U);
    attn<<<4096, 128>>>(lp);
    fused_fin<<<138, 256>>>(H, thr, out);
    if (out_size > Nn * Dd) orth_reduce<<<1, 32>>>(out + (size_t)Nn * Dd);
}